// round 2
// baseline (speedup 1.0000x reference)
#include <cuda_runtime.h>
#include <math.h>

// ---------------- problem constants ----------------
#define BB 2
#define SQ 1024
#define D_ 2048
#define HN 16
#define HD 128
#define NTOK (BB*SQ)       // 2048
#define EE 8
#define DE_ 704
#define NSLOT (NTOK*2)     // 4096 (top-2 per token)

// ---------------- scratch (device globals: no allocations allowed) ----------------
__device__ float g_xn  [NTOK*D_];
__device__ float g_q   [NTOK*D_];
__device__ float g_k   [NTOK*D_];
__device__ float g_v   [NTOK*D_];
__device__ float g_attn[NTOK*D_];
__device__ float g_h   [NTOK*D_];
__device__ float g_xn2 [NTOK*D_];
__device__ float g_gb  [NSLOT*DE_];
__device__ float g_ub  [NSLOT*DE_];
__device__ float g_op  [NSLOT*D_];
__device__ int   g_cnt [EE];
__device__ int   g_cur [EE];
__device__ int   g_off [EE];
__device__ int   g_tope[NTOK*2];
__device__ float g_topw[NTOK*2];
__device__ int   g_slot_tok[NSLOT];
__device__ float g_slot_w  [NSLOT];
__device__ int   g_tok_pos [NTOK*2];

// ---------------- RMSNorm ----------------
__global__ void rmsnorm_k(const float* __restrict__ x, const float* __restrict__ w,
                          float* __restrict__ o) {
    int n = blockIdx.x;
    const float* xr = x + (size_t)n * D_;
    float s = 0.f;
    for (int d = threadIdx.x; d < D_; d += 256) { float v = xr[d]; s += v * v; }
    __shared__ float red[256];
    red[threadIdx.x] = s; __syncthreads();
    for (int st = 128; st > 0; st >>= 1) {
        if (threadIdx.x < st) red[threadIdx.x] += red[threadIdx.x + st];
        __syncthreads();
    }
    float inv = rsqrtf(red[0] / (float)D_ + 1e-6f);
    float* orow = o + (size_t)n * D_;
    for (int d = threadIdx.x; d < D_; d += 256) orow[d] = xr[d] * inv * w[d];
}

// ---------------- generic NT GEMM: C[M,N] = A[M,K] * W[N,K]^T (+add) ----------------
// MODE 0: dense. MODE 1: A rows gathered via g_slot_tok (MoE up/gate).
// MODE 2: A rows are contiguous slots (MoE down). For MODE!=0 blockIdx.z = expert.
template<int MODE>
__global__ void __launch_bounds__(256, 2) gemm_nt(
    const float* __restrict__ A, const float* __restrict__ W,
    float* __restrict__ C, const float* __restrict__ addp,
    int M, int Nn, int Kk, long wstride)
{
    __shared__ float As[16][132];
    __shared__ float Bs[16][132];
    int e = blockIdx.z;
    int Mloc = M; int base = 0;
    const float* Wp = W;
    if (MODE != 0) { Mloc = g_cnt[e]; base = g_off[e]; Wp = W + (size_t)e * (size_t)wstride; }
    int m0 = blockIdx.y * 128;
    if (m0 >= Mloc) return;
    int n0 = blockIdx.x * 128;
    int tid = threadIdx.x;

    const float* aptr[2]; bool aval[2];
    const float* bptr[2]; bool bval[2];
#pragma unroll
    for (int i = 0; i < 2; i++) {
        int lr = (tid >> 2) + 64 * i;
        int gm = m0 + lr;
        bool v = gm < Mloc;
        int arow;
        if (MODE == 0)      arow = v ? gm : 0;
        else if (MODE == 1) arow = v ? g_slot_tok[base + gm] : 0;
        else                arow = v ? (base + gm) : 0;
        aval[i] = v;
        aptr[i] = A + (size_t)arow * Kk + (tid & 3) * 4;
        int gn = n0 + lr;
        bval[i] = gn < Nn;
        bptr[i] = Wp + (size_t)(bval[i] ? gn : 0) * Kk + (tid & 3) * 4;
    }

    float acc[8][8];
#pragma unroll
    for (int i = 0; i < 8; i++)
#pragma unroll
        for (int j = 0; j < 8; j++) acc[i][j] = 0.f;

    int ty = tid >> 4, tx = tid & 15;
    for (int k0 = 0; k0 < Kk; k0 += 16) {
#pragma unroll
        for (int i = 0; i < 2; i++) {
            int lr = (tid >> 2) + 64 * i;
            int kc = (tid & 3) * 4;
            float4 av = aval[i] ? *(const float4*)(aptr[i] + k0) : make_float4(0,0,0,0);
            As[kc+0][lr] = av.x; As[kc+1][lr] = av.y; As[kc+2][lr] = av.z; As[kc+3][lr] = av.w;
            float4 bv = bval[i] ? *(const float4*)(bptr[i] + k0) : make_float4(0,0,0,0);
            Bs[kc+0][lr] = bv.x; Bs[kc+1][lr] = bv.y; Bs[kc+2][lr] = bv.z; Bs[kc+3][lr] = bv.w;
        }
        __syncthreads();
#pragma unroll
        for (int kk = 0; kk < 16; kk++) {
            float a[8], b[8];
            *(float4*)&a[0] = *(const float4*)&As[kk][ty*8];
            *(float4*)&a[4] = *(const float4*)&As[kk][ty*8+4];
            *(float4*)&b[0] = *(const float4*)&Bs[kk][tx*8];
            *(float4*)&b[4] = *(const float4*)&Bs[kk][tx*8+4];
#pragma unroll
            for (int i = 0; i < 8; i++)
#pragma unroll
                for (int j = 0; j < 8; j++)
                    acc[i][j] = fmaf(a[i], b[j], acc[i][j]);
        }
        __syncthreads();
    }

#pragma unroll
    for (int i = 0; i < 8; i++) {
        int lr = ty * 8 + i;
        if (m0 + lr >= Mloc) continue;
        int crow = (MODE == 0) ? (m0 + lr) : (base + m0 + lr);
        size_t ro = (size_t)crow * Nn;
#pragma unroll
        for (int j = 0; j < 8; j++) {
            int gc = n0 + tx * 8 + j;
            if (gc < Nn) {
                float vv = acc[i][j];
                if (addp) vv += addp[ro + gc];
                C[ro + gc] = vv;
            }
        }
    }
}

// ---------------- RoPE (in-place on q,k) ----------------
__global__ void rope_k(float* __restrict__ q, float* __restrict__ k,
                       const int* __restrict__ pos) {
    int idx = blockIdx.x * 256 + threadIdx.x;
    if (idx >= NTOK * HN * 64) return;
    int j  = idx & 63;
    int hh = (idx >> 6) & 15;
    int t  = idx >> 10;
    float p = (float)pos[t];
    float inv = expf(-((float)(2 * j) / 128.0f) * 9.210340371976184f); // 10000^(-2j/128)
    float fr = p * inv;
    float sn, cs;
    sincosf(fr, &sn, &cs);
    size_t base = (size_t)t * D_ + hh * HD + j;
    float x1 = q[base], x2 = q[base + 64];
    q[base]      = x1 * cs - x2 * sn;
    q[base + 64] = x2 * cs + x1 * sn;
    x1 = k[base]; x2 = k[base + 64];
    k[base]      = x1 * cs - x2 * sn;
    k[base + 64] = x2 * cs + x1 * sn;
}

// ---------------- causal attention (streaming softmax) ----------------
#define BQ 16
#define BKT 32
__global__ void __launch_bounds__(256) attn_k(
    const float* __restrict__ Q, const float* __restrict__ Kb,
    const float* __restrict__ Vb, float* __restrict__ O)
{
    __shared__ float Qs[BQ][132];
    __shared__ float Ks[BKT][132];
    __shared__ float Vs[BKT][132];
    __shared__ float Ss[BQ][36];
    __shared__ float m_s[BQ], l_s[BQ], al_s[BQ];

    int q0 = blockIdx.x * BQ;
    int hh = blockIdx.y;
    int b  = blockIdx.z;
    int tid = threadIdx.x;
    int r = tid >> 4, c = tid & 15;

    size_t qbase = ((size_t)(b * SQ + q0)) * D_ + hh * HD;
#pragma unroll
    for (int i = 0; i < 2; i++) {
        int v4 = tid + i * 256;           // 0..511
        int row = v4 >> 5; int cc = (v4 & 31) * 4;
        *(float4*)&Qs[row][cc] = *(const float4*)(Q + qbase + (size_t)row * D_ + cc);
    }
    if (tid < BQ) { m_s[tid] = -1e30f; l_s[tid] = 0.f; }

    float acc[8];
#pragma unroll
    for (int i = 0; i < 8; i++) acc[i] = 0.f;

    for (int kt = 0; kt <= q0 + BQ - 1; kt += BKT) {
        __syncthreads();  // protect Qs (first iter) + Ks/Vs/Ss reuse
        size_t kb = ((size_t)(b * SQ + kt)) * D_ + hh * HD;
#pragma unroll
        for (int i = 0; i < 4; i++) {
            int v4 = tid + i * 256;       // 0..1023
            int row = v4 >> 5; int cc = (v4 & 31) * 4;
            *(float4*)&Ks[row][cc] = *(const float4*)(Kb + kb + (size_t)row * D_ + cc);
            *(float4*)&Vs[row][cc] = *(const float4*)(Vb + kb + (size_t)row * D_ + cc);
        }
        __syncthreads();

#pragma unroll
        for (int jj = 0; jj < 2; jj++) {
            int j = c * 2 + jj;
            float s = 0.f;
#pragma unroll
            for (int d4 = 0; d4 < 32; d4++) {
                float4 qv = *(const float4*)&Qs[r][d4 * 4];
                float4 kv = *(const float4*)&Ks[j][d4 * 4];
                s += qv.x * kv.x + qv.y * kv.y + qv.z * kv.z + qv.w * kv.w;
            }
            s *= 0.08838834764831845f;    // 1/sqrt(128)
            if (kt + j > q0 + r) s = -1e30f;
            Ss[r][j] = s;
        }
        __syncthreads();

        if (c == 0) {
            float mo = m_s[r];
            float mn = mo;
#pragma unroll
            for (int j = 0; j < BKT; j++) mn = fmaxf(mn, Ss[r][j]);
            float al = __expf(mo - mn);
            float sum = 0.f;
#pragma unroll
            for (int j = 0; j < BKT; j++) {
                float p = __expf(Ss[r][j] - mn);
                Ss[r][j] = p; sum += p;
            }
            l_s[r] = l_s[r] * al + sum;
            m_s[r] = mn; al_s[r] = al;
        }
        __syncthreads();

        float al = al_s[r];
#pragma unroll
        for (int i = 0; i < 8; i++) acc[i] *= al;
        for (int j = 0; j < BKT; j++) {
            float p = Ss[r][j];
#pragma unroll
            for (int q4 = 0; q4 < 2; q4++) {
                float4 vv = *(const float4*)&Vs[j][c * 4 + 64 * q4];
                acc[q4*4+0] = fmaf(p, vv.x, acc[q4*4+0]);
                acc[q4*4+1] = fmaf(p, vv.y, acc[q4*4+1]);
                acc[q4*4+2] = fmaf(p, vv.z, acc[q4*4+2]);
                acc[q4*4+3] = fmaf(p, vv.w, acc[q4*4+3]);
            }
        }
    }

    float linv = 1.f / l_s[r];
    size_t ob = ((size_t)(b * SQ + q0 + r)) * D_ + hh * HD;
#pragma unroll
    for (int q4 = 0; q4 < 2; q4++) {
        float4 ov = make_float4(acc[q4*4+0]*linv, acc[q4*4+1]*linv,
                                acc[q4*4+2]*linv, acc[q4*4+3]*linv);
        *(float4*)(O + ob + c * 4 + 64 * q4) = ov;
    }
}

// ---------------- MoE routing ----------------
__global__ void zero_k() {
    if (threadIdx.x < EE) { g_cnt[threadIdx.x] = 0; g_cur[threadIdx.x] = 0; }
}

__global__ void route1_k(const float* __restrict__ x, const float* __restrict__ gw) {
    int n = blockIdx.x;
    float part[EE];
#pragma unroll
    for (int e = 0; e < EE; e++) part[e] = 0.f;
    for (int d = threadIdx.x; d < D_; d += 256) {
        float xv = x[(size_t)n * D_ + d];
#pragma unroll
        for (int e = 0; e < EE; e++) part[e] = fmaf(xv, gw[e * D_ + d], part[e]);
    }
    __shared__ float red[256];
    __shared__ float lg[EE];
    for (int e = 0; e < EE; e++) {
        red[threadIdx.x] = part[e]; __syncthreads();
        for (int st = 128; st > 0; st >>= 1) {
            if (threadIdx.x < st) red[threadIdx.x] += red[threadIdx.x + st];
            __syncthreads();
        }
        if (threadIdx.x == 0) lg[e] = red[0];
        __syncthreads();
    }
    if (threadIdx.x == 0) {
        int i0 = 0; float b0 = lg[0];
        for (int e = 1; e < EE; e++) if (lg[e] > b0) { b0 = lg[e]; i0 = e; }
        int i1 = -1; float b1 = -1e30f;
        for (int e = 0; e < EE; e++) { if (e == i0) continue; if (lg[e] > b1) { b1 = lg[e]; i1 = e; } }
        float m = fmaxf(b0, b1);
        float w0 = __expf(b0 - m), w1 = __expf(b1 - m);
        float s = w0 + w1; w0 /= s; w1 /= s;
        g_tope[n*2] = i0; g_tope[n*2+1] = i1;
        g_topw[n*2] = w0; g_topw[n*2+1] = w1;
        atomicAdd(&g_cnt[i0], 1); atomicAdd(&g_cnt[i1], 1);
    }
}

__global__ void scan_k() {
    int o = 0;
    for (int e = 0; e < EE; e++) { g_off[e] = o; o += g_cnt[e]; }
}

__global__ void assign_k() {
    int n = blockIdx.x * 256 + threadIdx.x;
    if (n >= NTOK) return;
#pragma unroll
    for (int kk = 0; kk < 2; kk++) {
        int e = g_tope[n*2 + kk];
        int p = g_off[e] + atomicAdd(&g_cur[e], 1);
        g_slot_tok[p] = n;
        g_slot_w[p]   = g_topw[n*2 + kk];
        g_tok_pos[n*2 + kk] = p;
    }
}

__global__ void swiglu_k() {
    int i = blockIdx.x * 256 + threadIdx.x;
    if (i >= NSLOT * DE_) return;
    float g = g_gb[i], u = g_ub[i];
    float sig = 1.f / (1.f + __expf(-g));
    g_gb[i] = g * sig * u;
}

__global__ void final_k(float* __restrict__ out) {
    int n = blockIdx.x;
    int p0 = g_tok_pos[n*2], p1 = g_tok_pos[n*2 + 1];
    float w0 = g_slot_w[p0], w1 = g_slot_w[p1];
    size_t hb = (size_t)n * D_;
    for (int d = threadIdx.x * 4; d < D_; d += 1024) {
        float4 hv = *(const float4*)(g_h + hb + d);
        float4 a  = *(const float4*)(g_op + (size_t)p0 * D_ + d);
        float4 b4 = *(const float4*)(g_op + (size_t)p1 * D_ + d);
        float4 o;
        o.x = hv.x + w0 * a.x + w1 * b4.x;
        o.y = hv.y + w0 * a.y + w1 * b4.y;
        o.z = hv.z + w0 * a.z + w1 * b4.z;
        o.w = hv.w + w0 * a.w + w1 * b4.w;
        *(float4*)(out + hb + d) = o;
    }
}

// ---------------- launcher ----------------
extern "C" void kernel_launch(void* const* d_in, const int* in_sizes, int n_in,
                              void* d_out, int out_size) {
    const float* hidden = (const float*)d_in[0];
    const float* ln1    = (const float*)d_in[1];
    const float* ln2    = (const float*)d_in[2];
    const float* qw     = (const float*)d_in[3];
    const float* kw     = (const float*)d_in[4];
    const float* vw     = (const float*)d_in[5];
    const float* ow     = (const float*)d_in[6];
    const float* gw     = (const float*)d_in[7];
    const float* egw    = (const float*)d_in[8];
    const float* euw    = (const float*)d_in[9];
    const float* edw    = (const float*)d_in[10];
    const int*   pos    = (const int*)d_in[11];
    float* out = (float*)d_out;

    float *xn, *qb, *kb, *vb, *ab, *hb, *x2, *gb, *ub, *op;
    cudaGetSymbolAddress((void**)&xn, g_xn);
    cudaGetSymbolAddress((void**)&qb, g_q);
    cudaGetSymbolAddress((void**)&kb, g_k);
    cudaGetSymbolAddress((void**)&vb, g_v);
    cudaGetSymbolAddress((void**)&ab, g_attn);
    cudaGetSymbolAddress((void**)&hb, g_h);
    cudaGetSymbolAddress((void**)&x2, g_xn2);
    cudaGetSymbolAddress((void**)&gb, g_gb);
    cudaGetSymbolAddress((void**)&ub, g_ub);
    cudaGetSymbolAddress((void**)&op, g_op);

    // 1. pre-attention RMSNorm
    rmsnorm_k<<<NTOK, 256>>>(hidden, ln1, xn);

    // 2. QKV projections
    dim3 gdense(D_ / 128, NTOK / 128, 1);
    gemm_nt<0><<<gdense, 256>>>(xn, qw, qb, nullptr, NTOK, D_, D_, 0);
    gemm_nt<0><<<gdense, 256>>>(xn, kw, kb, nullptr, NTOK, D_, D_, 0);
    gemm_nt<0><<<gdense, 256>>>(xn, vw, vb, nullptr, NTOK, D_, D_, 0);

    // 3. RoPE
    rope_k<<<(NTOK * HN * 64) / 256, 256>>>(qb, kb, pos);

    // 4. causal attention
    attn_k<<<dim3(SQ / BQ, HN, BB), 256>>>(qb, kb, vb, ab);

    // 5. O projection + residual
    gemm_nt<0><<<gdense, 256>>>(ab, ow, hb, hidden, NTOK, D_, D_, 0);

    // 6. post-attention RMSNorm
    rmsnorm_k<<<NTOK, 256>>>(hb, ln2, x2);

    // 7. routing: logits -> top2 -> softmax weights -> gather lists
    zero_k<<<1, 32>>>();
    route1_k<<<NTOK, 256>>>(x2, gw);
    scan_k<<<1, 1>>>();
    assign_k<<<NTOK / 256, 256>>>();

    // 8. MoE expert GEMMs (gathered rows, per-expert weights)
    gemm_nt<1><<<dim3((DE_ + 127) / 128, NTOK / 128, EE), 256>>>(
        x2, egw, gb, nullptr, 0, DE_, D_, (long)DE_ * D_);
    gemm_nt<1><<<dim3((DE_ + 127) / 128, NTOK / 128, EE), 256>>>(
        x2, euw, ub, nullptr, 0, DE_, D_, (long)DE_ * D_);
    swiglu_k<<<(NSLOT * DE_ + 255) / 256, 256>>>();
    gemm_nt<2><<<dim3(D_ / 128, NTOK / 128, EE), 256>>>(
        gb, edw, op, nullptr, 0, D_, DE_, (long)D_ * DE_);

    // 9. weighted combine + residual
    final_k<<<NTOK, 256>>>(out);
}

// round 7
// speedup vs baseline: 1.5368x; 1.5368x over previous
#include <cuda_runtime.h>
#include <cuda_bf16.h>
#include <math.h>
#include <stdint.h>

// ---------------- problem constants ----------------
#define BB 2
#define SQ 1024
#define D_ 2048
#define HN 16
#define HD 128
#define NTOK (BB*SQ)       // 2048
#define EE 8
#define DE_ 704
#define NSLOT (NTOK*2)     // 4096 (top-2 per token)

// ---------------- scratch (device globals: no allocations allowed) ----------------
__device__ float g_xn  [NTOK*D_];
__device__ float g_q   [NTOK*D_];
__device__ float g_k   [NTOK*D_];
__device__ float g_v   [NTOK*D_];
__device__ float g_attn[NTOK*D_];
__device__ float g_h   [NTOK*D_];
__device__ float g_xn2 [NTOK*D_];
__device__ float g_gb  [NSLOT*DE_];
__device__ float g_ub  [NSLOT*DE_];
__device__ float g_op  [NSLOT*D_];
__device__ int   g_cnt [EE];
__device__ int   g_cur [EE];
__device__ int   g_off [EE];
__device__ int   g_tope[NTOK*2];
__device__ float g_topw[NTOK*2];
__device__ int   g_slot_tok[NSLOT];
__device__ float g_slot_w  [NSLOT];
__device__ int   g_tok_pos [NTOK*2];

// ---------------- helpers ----------------
__device__ __forceinline__ void mma_bf16(float* c, const uint32_t* a,
                                         uint32_t b0, uint32_t b1) {
    asm volatile(
        "mma.sync.aligned.m16n8k16.row.col.f32.bf16.bf16.f32 "
        "{%0,%1,%2,%3}, {%4,%5,%6,%7}, {%8,%9}, {%0,%1,%2,%3};"
        : "+f"(c[0]), "+f"(c[1]), "+f"(c[2]), "+f"(c[3])
        : "r"(a[0]), "r"(a[1]), "r"(a[2]), "r"(a[3]), "r"(b0), "r"(b1));
}

// split x -> (hi, lo) bf16 pair, packed per 2 adjacent k: returns (w_hi, w_lo)
__device__ __forceinline__ void split2(float x0, float x1, uint32_t& wh, uint32_t& wl) {
    __nv_bfloat16 h0 = __float2bfloat16(x0);
    __nv_bfloat16 h1 = __float2bfloat16(x1);
    __nv_bfloat16 l0 = __float2bfloat16(x0 - __bfloat162float(h0));
    __nv_bfloat16 l1 = __float2bfloat16(x1 - __bfloat162float(h1));
    wh = ((uint32_t)__bfloat16_as_ushort(h1) << 16) | __bfloat16_as_ushort(h0);
    wl = ((uint32_t)__bfloat16_as_ushort(l1) << 16) | __bfloat16_as_ushort(l0);
}

// ---------------- tensor-core (mma.sync bf16x3) GEMM ----------------
// C[M,N] = A[M,K] * W[N,K]^T (+add)
// MODE 0: dense. MODE 1: A rows gathered via g_slot_tok. MODE 2: A rows contiguous slots.
#define TM 128
#define TN 128
#define BK 16
#define RS 12   // row stride in 32-bit words (16 bf16 data = 8 words + 4 pad) -> conflict-free

template<int MODE>
__global__ void __launch_bounds__(256) gemm_mma(
    const float* __restrict__ A, const float* __restrict__ W,
    float* __restrict__ C, const float* __restrict__ addp,
    int M, int Nn, int Kk, long wstride)
{
    __shared__ uint32_t Ah[2][TM][RS];
    __shared__ uint32_t Al[2][TM][RS];
    __shared__ uint32_t Bh[2][TN][RS];
    __shared__ uint32_t Bl[2][TN][RS];

    int e = blockIdx.z;
    int Mloc = M, base = 0;
    const float* Wp = W;
    if (MODE != 0) { Mloc = g_cnt[e]; base = g_off[e]; Wp = W + (size_t)e * (size_t)wstride; }
    int m0 = blockIdx.y * TM;
    if (m0 >= Mloc) return;
    int n0 = blockIdx.x * TN;
    int tid = threadIdx.x;

    // --- per-thread staging slots: 2 float4 for A, 2 for B per stage ---
    const float* aP[2]; const float* bP[2];
    int rowL[2], c4L[2];
    bool aV[2], bV[2];
#pragma unroll
    for (int i = 0; i < 2; i++) {
        int v = tid + i * 256;          // 0..511
        int row = v >> 2, c4 = v & 3;
        rowL[i] = row; c4L[i] = c4;
        int gm = m0 + row;
        bool av = gm < Mloc;
        int arow;
        if (MODE == 0)      arow = av ? gm : 0;
        else if (MODE == 1) arow = av ? g_slot_tok[base + gm] : 0;
        else                arow = av ? (base + gm) : 0;
        aV[i] = av;
        aP[i] = A + (size_t)arow * Kk + c4 * 4;
        int gn = n0 + row;
        bV[i] = gn < Nn;
        bP[i] = Wp + (size_t)(bV[i] ? gn : 0) * Kk + c4 * 4;
    }

    int lane = tid & 31, g = lane >> 2, tg = lane & 3;
    int wm = (tid >> 5) & 3;     // 4 warps over M: 32 rows each
    int wn = tid >> 7;           // 2 warps over N: 64 cols each
    int mbase = wm * 32, nbase = wn * 64;

    float acc[2][8][4];
#pragma unroll
    for (int mt = 0; mt < 2; mt++)
#pragma unroll
        for (int nt = 0; nt < 8; nt++)
#pragma unroll
            for (int q = 0; q < 4; q++) acc[mt][nt][q] = 0.f;

    int nk = Kk / BK;
    float4 ra[2], rb[2];
#pragma unroll
    for (int i = 0; i < 2; i++) {
        ra[i] = aV[i] ? *(const float4*)(aP[i]) : make_float4(0,0,0,0);
        rb[i] = bV[i] ? *(const float4*)(bP[i]) : make_float4(0,0,0,0);
    }

    int buf = 0;
    for (int it = 0; it < nk; it++) {
        // split+store current regs to smem
#pragma unroll
        for (int i = 0; i < 2; i++) {
            int r = rowL[i], w0 = c4L[i] * 2;
            uint32_t h0, l0, h1, l1;
            split2(ra[i].x, ra[i].y, h0, l0);
            split2(ra[i].z, ra[i].w, h1, l1);
            Ah[buf][r][w0] = h0; Ah[buf][r][w0+1] = h1;
            Al[buf][r][w0] = l0; Al[buf][r][w0+1] = l1;
            split2(rb[i].x, rb[i].y, h0, l0);
            split2(rb[i].z, rb[i].w, h1, l1);
            Bh[buf][r][w0] = h0; Bh[buf][r][w0+1] = h1;
            Bl[buf][r][w0] = l0; Bl[buf][r][w0+1] = l1;
        }
        // issue next-stage global loads (overlap with compute)
        if (it + 1 < nk) {
            int k0 = (it + 1) * BK;
#pragma unroll
            for (int i = 0; i < 2; i++) {
                ra[i] = aV[i] ? *(const float4*)(aP[i] + k0) : make_float4(0,0,0,0);
                rb[i] = bV[i] ? *(const float4*)(bP[i] + k0) : make_float4(0,0,0,0);
            }
        }
        __syncthreads();

        // compute on buf: one k16 slice, 3 passes (AhBh + AhBl + AlBh)
        uint32_t ah[2][4], al[2][4];
#pragma unroll
        for (int mt = 0; mt < 2; mt++) {
            int r0 = mbase + mt * 16 + g;
            ah[mt][0] = Ah[buf][r0][tg];     ah[mt][1] = Ah[buf][r0+8][tg];
            ah[mt][2] = Ah[buf][r0][tg+4];   ah[mt][3] = Ah[buf][r0+8][tg+4];
            al[mt][0] = Al[buf][r0][tg];     al[mt][1] = Al[buf][r0+8][tg];
            al[mt][2] = Al[buf][r0][tg+4];   al[mt][3] = Al[buf][r0+8][tg+4];
        }
#pragma unroll
        for (int nt = 0; nt < 8; nt++) {
            int nr = nbase + nt * 8 + g;
            uint32_t bh0 = Bh[buf][nr][tg], bh1 = Bh[buf][nr][tg+4];
            uint32_t bl0 = Bl[buf][nr][tg], bl1 = Bl[buf][nr][tg+4];
#pragma unroll
            for (int mt = 0; mt < 2; mt++) {
                mma_bf16(acc[mt][nt], ah[mt], bh0, bh1);
                mma_bf16(acc[mt][nt], ah[mt], bl0, bl1);
                mma_bf16(acc[mt][nt], al[mt], bh0, bh1);
            }
        }
        buf ^= 1;
        // single barrier per stage is safe with 2 buffers (see rotation proof)
    }

    // --- epilogue: c0/c1 -> (row g, cols 2tg,2tg+1), c2/c3 -> row g+8
#pragma unroll
    for (int mt = 0; mt < 2; mt++) {
#pragma unroll
        for (int nt = 0; nt < 8; nt++) {
            int gc = n0 + nbase + nt * 8 + tg * 2;
            if (gc >= Nn) continue;
            int gm0 = m0 + mbase + mt * 16 + g;
#pragma unroll
            for (int hrow = 0; hrow < 2; hrow++) {
                int gm = gm0 + hrow * 8;
                if (gm >= Mloc) continue;
                int crow = (MODE == 0) ? gm : (base + gm);
                size_t off = (size_t)crow * Nn + gc;
                float2 vv = make_float2(acc[mt][nt][hrow * 2], acc[mt][nt][hrow * 2 + 1]);
                if (MODE == 0 && addp) {
                    float2 rv = *(const float2*)(addp + off);
                    vv.x += rv.x; vv.y += rv.y;
                }
                *(float2*)(C + off) = vv;
            }
        }
    }
}

// ---------------- RMSNorm ----------------
__global__ void rmsnorm_k(const float* __restrict__ x, const float* __restrict__ w,
                          float* __restrict__ o) {
    int n = blockIdx.x;
    const float* xr = x + (size_t)n * D_;
    float s = 0.f;
    for (int d = threadIdx.x; d < D_; d += 256) { float v = xr[d]; s += v * v; }
    __shared__ float red[256];
    red[threadIdx.x] = s; __syncthreads();
    for (int st = 128; st > 0; st >>= 1) {
        if (threadIdx.x < st) red[threadIdx.x] += red[threadIdx.x + st];
        __syncthreads();
    }
    float inv = rsqrtf(red[0] / (float)D_ + 1e-6f);
    float* orow = o + (size_t)n * D_;
    for (int d = threadIdx.x; d < D_; d += 256) orow[d] = xr[d] * inv * w[d];
}

// ---------------- RoPE (in-place on q,k) ----------------
__global__ void rope_k(float* __restrict__ q, float* __restrict__ k,
                       const int* __restrict__ pos) {
    int idx = blockIdx.x * 256 + threadIdx.x;
    if (idx >= NTOK * HN * 64) return;
    int j  = idx & 63;
    int hh = (idx >> 6) & 15;
    int t  = idx >> 10;
    float p = (float)pos[t];
    float inv = expf(-((float)(2 * j) / 128.0f) * 9.210340371976184f);
    float fr = p * inv;
    float sn, cs;
    sincosf(fr, &sn, &cs);
    size_t base = (size_t)t * D_ + hh * HD + j;
    float x1 = q[base], x2 = q[base + 64];
    q[base]      = x1 * cs - x2 * sn;
    q[base + 64] = x2 * cs + x1 * sn;
    x1 = k[base]; x2 = k[base + 64];
    k[base]      = x1 * cs - x2 * sn;
    k[base + 64] = x2 * cs + x1 * sn;
}

// ---------------- causal attention (streaming softmax) ----------------
#define BQ 16
#define BKT 32
__global__ void __launch_bounds__(256) attn_k(
    const float* __restrict__ Q, const float* __restrict__ Kb,
    const float* __restrict__ Vb, float* __restrict__ O)
{
    __shared__ float Qs[BQ][132];
    __shared__ float Ks[BKT][132];
    __shared__ float Vs[BKT][132];
    __shared__ float Ss[BQ][36];
    __shared__ float m_s[BQ], l_s[BQ], al_s[BQ];

    int q0 = blockIdx.x * BQ;
    int hh = blockIdx.y;
    int b  = blockIdx.z;
    int tid = threadIdx.x;
    int r = tid >> 4, c = tid & 15;

    size_t qbase = ((size_t)(b * SQ + q0)) * D_ + hh * HD;
#pragma unroll
    for (int i = 0; i < 2; i++) {
        int v4 = tid + i * 256;
        int row = v4 >> 5; int cc = (v4 & 31) * 4;
        *(float4*)&Qs[row][cc] = *(const float4*)(Q + qbase + (size_t)row * D_ + cc);
    }
    if (tid < BQ) { m_s[tid] = -1e30f; l_s[tid] = 0.f; }

    float acc[8];
#pragma unroll
    for (int i = 0; i < 8; i++) acc[i] = 0.f;

    for (int kt = 0; kt <= q0 + BQ - 1; kt += BKT) {
        __syncthreads();
        size_t kb = ((size_t)(b * SQ + kt)) * D_ + hh * HD;
#pragma unroll
        for (int i = 0; i < 4; i++) {
            int v4 = tid + i * 256;
            int row = v4 >> 5; int cc = (v4 & 31) * 4;
            *(float4*)&Ks[row][cc] = *(const float4*)(Kb + kb + (size_t)row * D_ + cc);
            *(float4*)&Vs[row][cc] = *(const float4*)(Vb + kb + (size_t)row * D_ + cc);
        }
        __syncthreads();

#pragma unroll
        for (int jj = 0; jj < 2; jj++) {
            int j = c * 2 + jj;
            float s = 0.f;
#pragma unroll
            for (int d4 = 0; d4 < 32; d4++) {
                float4 qv = *(const float4*)&Qs[r][d4 * 4];
                float4 kv = *(const float4*)&Ks[j][d4 * 4];
                s += qv.x * kv.x + qv.y * kv.y + qv.z * kv.z + qv.w * kv.w;
            }
            s *= 0.08838834764831845f;
            if (kt + j > q0 + r) s = -1e30f;
            Ss[r][j] = s;
        }
        __syncthreads();

        if (c == 0) {
            float mo = m_s[r];
            float mn = mo;
#pragma unroll
            for (int j = 0; j < BKT; j++) mn = fmaxf(mn, Ss[r][j]);
            float al = __expf(mo - mn);
            float sum = 0.f;
#pragma unroll
            for (int j = 0; j < BKT; j++) {
                float p = __expf(Ss[r][j] - mn);
                Ss[r][j] = p; sum += p;
            }
            l_s[r] = l_s[r] * al + sum;
            m_s[r] = mn; al_s[r] = al;
        }
        __syncthreads();

        float al = al_s[r];
#pragma unroll
        for (int i = 0; i < 8; i++) acc[i] *= al;
        for (int j = 0; j < BKT; j++) {
            float p = Ss[r][j];
#pragma unroll
            for (int q4 = 0; q4 < 2; q4++) {
                float4 vv = *(const float4*)&Vs[j][c * 4 + 64 * q4];
                acc[q4*4+0] = fmaf(p, vv.x, acc[q4*4+0]);
                acc[q4*4+1] = fmaf(p, vv.y, acc[q4*4+1]);
                acc[q4*4+2] = fmaf(p, vv.z, acc[q4*4+2]);
                acc[q4*4+3] = fmaf(p, vv.w, acc[q4*4+3]);
            }
        }
    }

    float linv = 1.f / l_s[r];
    size_t ob = ((size_t)(b * SQ + q0 + r)) * D_ + hh * HD;
#pragma unroll
    for (int q4 = 0; q4 < 2; q4++) {
        float4 ov = make_float4(acc[q4*4+0]*linv, acc[q4*4+1]*linv,
                                acc[q4*4+2]*linv, acc[q4*4+3]*linv);
        *(float4*)(O + ob + c * 4 + 64 * q4) = ov;
    }
}

// ---------------- MoE routing ----------------
__global__ void zero_k() {
    if (threadIdx.x < EE) { g_cnt[threadIdx.x] = 0; g_cur[threadIdx.x] = 0; }
}

__global__ void route1_k(const float* __restrict__ x, const float* __restrict__ gw) {
    int n = blockIdx.x;
    float part[EE];
#pragma unroll
    for (int e = 0; e < EE; e++) part[e] = 0.f;
    for (int d = threadIdx.x; d < D_; d += 256) {
        float xv = x[(size_t)n * D_ + d];
#pragma unroll
        for (int e = 0; e < EE; e++) part[e] = fmaf(xv, gw[e * D_ + d], part[e]);
    }
    __shared__ float red[256];
    __shared__ float lg[EE];
    for (int e = 0; e < EE; e++) {
        red[threadIdx.x] = part[e]; __syncthreads();
        for (int st = 128; st > 0; st >>= 1) {
            if (threadIdx.x < st) red[threadIdx.x] += red[threadIdx.x + st];
            __syncthreads();
        }
        if (threadIdx.x == 0) lg[e] = red[0];
        __syncthreads();
    }
    if (threadIdx.x == 0) {
        int i0 = 0; float b0 = lg[0];
        for (int e = 1; e < EE; e++) if (lg[e] > b0) { b0 = lg[e]; i0 = e; }
        int i1 = -1; float b1 = -1e30f;
        for (int e = 0; e < EE; e++) { if (e == i0) continue; if (lg[e] > b1) { b1 = lg[e]; i1 = e; } }
        float m = fmaxf(b0, b1);
        float w0 = __expf(b0 - m), w1 = __expf(b1 - m);
        float s = w0 + w1; w0 /= s; w1 /= s;
        g_tope[n*2] = i0; g_tope[n*2+1] = i1;
        g_topw[n*2] = w0; g_topw[n*2+1] = w1;
        atomicAdd(&g_cnt[i0], 1); atomicAdd(&g_cnt[i1], 1);
    }
}

__global__ void scan_k() {
    int o = 0;
    for (int e = 0; e < EE; e++) { g_off[e] = o; o += g_cnt[e]; }
}

__global__ void assign_k() {
    int n = blockIdx.x * 256 + threadIdx.x;
    if (n >= NTOK) return;
#pragma unroll
    for (int kk = 0; kk < 2; kk++) {
        int e = g_tope[n*2 + kk];
        int p = g_off[e] + atomicAdd(&g_cur[e], 1);
        g_slot_tok[p] = n;
        g_slot_w[p]   = g_topw[n*2 + kk];
        g_tok_pos[n*2 + kk] = p;
    }
}

__global__ void swiglu_k() {
    int i = blockIdx.x * 256 + threadIdx.x;
    if (i >= NSLOT * DE_) return;
    float g = g_gb[i], u = g_ub[i];
    float sig = 1.f / (1.f + __expf(-g));
    g_gb[i] = g * sig * u;
}

__global__ void final_k(float* __restrict__ out) {
    int n = blockIdx.x;
    int p0 = g_tok_pos[n*2], p1 = g_tok_pos[n*2 + 1];
    float w0 = g_slot_w[p0], w1 = g_slot_w[p1];
    size_t hb = (size_t)n * D_;
    for (int d = threadIdx.x * 4; d < D_; d += 1024) {
        float4 hv = *(const float4*)(g_h + hb + d);
        float4 a  = *(const float4*)(g_op + (size_t)p0 * D_ + d);
        float4 b4 = *(const float4*)(g_op + (size_t)p1 * D_ + d);
        float4 o;
        o.x = hv.x + w0 * a.x + w1 * b4.x;
        o.y = hv.y + w0 * a.y + w1 * b4.y;
        o.z = hv.z + w0 * a.z + w1 * b4.z;
        o.w = hv.w + w0 * a.w + w1 * b4.w;
        *(float4*)(out + hb + d) = o;
    }
}

// ---------------- launcher ----------------
extern "C" void kernel_launch(void* const* d_in, const int* in_sizes, int n_in,
                              void* d_out, int out_size) {
    const float* hidden = (const float*)d_in[0];
    const float* ln1    = (const float*)d_in[1];
    const float* ln2    = (const float*)d_in[2];
    const float* qw     = (const float*)d_in[3];
    const float* kw     = (const float*)d_in[4];
    const float* vw     = (const float*)d_in[5];
    const float* ow     = (const float*)d_in[6];
    const float* gw     = (const float*)d_in[7];
    const float* egw    = (const float*)d_in[8];
    const float* euw    = (const float*)d_in[9];
    const float* edw    = (const float*)d_in[10];
    const int*   pos    = (const int*)d_in[11];
    float* out = (float*)d_out;

    float *xn, *qb, *kb, *vb, *ab, *hb, *x2, *gb, *ub, *op;
    cudaGetSymbolAddress((void**)&xn, g_xn);
    cudaGetSymbolAddress((void**)&qb, g_q);
    cudaGetSymbolAddress((void**)&kb, g_k);
    cudaGetSymbolAddress((void**)&vb, g_v);
    cudaGetSymbolAddress((void**)&ab, g_attn);
    cudaGetSymbolAddress((void**)&hb, g_h);
    cudaGetSymbolAddress((void**)&x2, g_xn2);
    cudaGetSymbolAddress((void**)&gb, g_gb);
    cudaGetSymbolAddress((void**)&ub, g_ub);
    cudaGetSymbolAddress((void**)&op, g_op);

    // 1. pre-attention RMSNorm
    rmsnorm_k<<<NTOK, 256>>>(hidden, ln1, xn);

    // 2. QKV projections (mma.sync bf16x3)
    dim3 gdense(D_ / TN, NTOK / TM, 1);
    gemm_mma<0><<<gdense, 256>>>(xn, qw, qb, nullptr, NTOK, D_, D_, 0);
    gemm_mma<0><<<gdense, 256>>>(xn, kw, kb, nullptr, NTOK, D_, D_, 0);
    gemm_mma<0><<<gdense, 256>>>(xn, vw, vb, nullptr, NTOK, D_, D_, 0);

    // 3. RoPE
    rope_k<<<(NTOK * HN * 64) / 256, 256>>>(qb, kb, pos);

    // 4. causal attention
    attn_k<<<dim3(SQ / BQ, HN, BB), 256>>>(qb, kb, vb, ab);

    // 5. O projection + residual
    gemm_mma<0><<<gdense, 256>>>(ab, ow, hb, hidden, NTOK, D_, D_, 0);

    // 6. post-attention RMSNorm
    rmsnorm_k<<<NTOK, 256>>>(hb, ln2, x2);

    // 7. routing
    zero_k<<<1, 32>>>();
    route1_k<<<NTOK, 256>>>(x2, gw);
    scan_k<<<1, 1>>>();
    assign_k<<<NTOK / 256, 256>>>();

    // 8. MoE expert GEMMs (mma.sync bf16x3, gathered rows)
    gemm_mma<1><<<dim3((DE_ + TN - 1) / TN, 16, EE), 256>>>(
        x2, egw, gb, nullptr, 0, DE_, D_, (long)DE_ * D_);
    gemm_mma<1><<<dim3((DE_ + TN - 1) / TN, 16, EE), 256>>>(
        x2, euw, ub, nullptr, 0, DE_, D_, (long)DE_ * D_);
    swiglu_k<<<(NSLOT * DE_ + 255) / 256, 256>>>();
    gemm_mma<2><<<dim3(D_ / TN, 16, EE), 256>>>(
        gb, edw, op, nullptr, 0, D_, DE_, (long)D_ * DE_);

    // 9. weighted combine + residual
    final_k<<<NTOK, 256>>>(out);
}

// round 8
// speedup vs baseline: 2.1245x; 1.3824x over previous
#include <cuda_runtime.h>
#include <cuda_bf16.h>
#include <math.h>
#include <stdint.h>

// ---------------- problem constants ----------------
#define BB 2
#define SQ 1024
#define D_ 2048
#define HN 16
#define HD 128
#define NTOK (BB*SQ)       // 2048
#define EE 8
#define DE_ 704
#define NSLOT (NTOK*2)     // 4096 (top-2 per token)

// ---------------- scratch (device globals: no allocations allowed) ----------------
__device__ float g_xn  [NTOK*D_];
__device__ float g_q   [NTOK*D_];
__device__ float g_k   [NTOK*D_];
__device__ float g_v   [NTOK*D_];
__device__ float g_attn[NTOK*D_];
__device__ float g_h   [NTOK*D_];
__device__ float g_xn2 [NTOK*D_];
__device__ float g_gb  [NSLOT*DE_];
__device__ float g_ub  [NSLOT*DE_];
__device__ float g_op  [NSLOT*D_];
__device__ int   g_cnt [EE];
__device__ int   g_cur [EE];
__device__ int   g_off [EE];
__device__ int   g_tope[NTOK*2];
__device__ float g_topw[NTOK*2];
__device__ int   g_slot_tok[NSLOT];
__device__ float g_slot_w  [NSLOT];
__device__ int   g_tok_pos [NTOK*2];
// bf16 hi/lo splits for attention
__device__ __nv_bfloat16 g_qh[NTOK*D_], g_ql[NTOK*D_];
__device__ __nv_bfloat16 g_kh[NTOK*D_], g_kl[NTOK*D_];
__device__ __nv_bfloat16 g_vth[NTOK*D_], g_vtl[NTOK*D_];   // [b*HN+h][HD][SQ]

// ---------------- helpers ----------------
__device__ __forceinline__ void mma_bf16(float* c, const uint32_t* a,
                                         uint32_t b0, uint32_t b1) {
    asm volatile(
        "mma.sync.aligned.m16n8k16.row.col.f32.bf16.bf16.f32 "
        "{%0,%1,%2,%3}, {%4,%5,%6,%7}, {%8,%9}, {%0,%1,%2,%3};"
        : "+f"(c[0]), "+f"(c[1]), "+f"(c[2]), "+f"(c[3])
        : "r"(a[0]), "r"(a[1]), "r"(a[2]), "r"(a[3]), "r"(b0), "r"(b1));
}

// split x -> (hi, lo) bf16 pair, packed per 2 adjacent k: returns (w_hi, w_lo)
__device__ __forceinline__ void split2(float x0, float x1, uint32_t& wh, uint32_t& wl) {
    __nv_bfloat16 h0 = __float2bfloat16(x0);
    __nv_bfloat16 h1 = __float2bfloat16(x1);
    __nv_bfloat16 l0 = __float2bfloat16(x0 - __bfloat162float(h0));
    __nv_bfloat16 l1 = __float2bfloat16(x1 - __bfloat162float(h1));
    wh = ((uint32_t)__bfloat16_as_ushort(h1) << 16) | __bfloat16_as_ushort(h0);
    wl = ((uint32_t)__bfloat16_as_ushort(l1) << 16) | __bfloat16_as_ushort(l0);
}
__device__ __forceinline__ void split1(float x, __nv_bfloat16& h, __nv_bfloat16& l) {
    h = __float2bfloat16(x);
    l = __float2bfloat16(x - __bfloat162float(h));
}

// ---------------- tensor-core (mma.sync bf16x3) GEMM ----------------
// C[M,N] = A[M,K] * W[N,K]^T (+add)
// MODE 0: dense. MODE 1: A rows gathered via g_slot_tok. MODE 2: A rows contiguous slots.
#define TM 128
#define TN 128
#define BK 16
#define RS 12   // row stride in 32-bit words -> conflict-free

template<int MODE>
__global__ void __launch_bounds__(256) gemm_mma(
    const float* __restrict__ A, const float* __restrict__ W,
    float* __restrict__ C, const float* __restrict__ addp,
    int M, int Nn, int Kk, long wstride)
{
    __shared__ uint32_t Ah[2][TM][RS];
    __shared__ uint32_t Al[2][TM][RS];
    __shared__ uint32_t Bh[2][TN][RS];
    __shared__ uint32_t Bl[2][TN][RS];

    int e = blockIdx.z;
    int Mloc = M, base = 0;
    const float* Wp = W;
    if (MODE != 0) { Mloc = g_cnt[e]; base = g_off[e]; Wp = W + (size_t)e * (size_t)wstride; }
    int m0 = blockIdx.y * TM;
    if (m0 >= Mloc) return;
    int n0 = blockIdx.x * TN;
    int tid = threadIdx.x;

    const float* aP[2]; const float* bP[2];
    int rowL[2], c4L[2];
    bool aV[2], bV[2];
#pragma unroll
    for (int i = 0; i < 2; i++) {
        int v = tid + i * 256;
        int row = v >> 2, c4 = v & 3;
        rowL[i] = row; c4L[i] = c4;
        int gm = m0 + row;
        bool av = gm < Mloc;
        int arow;
        if (MODE == 0)      arow = av ? gm : 0;
        else if (MODE == 1) arow = av ? g_slot_tok[base + gm] : 0;
        else                arow = av ? (base + gm) : 0;
        aV[i] = av;
        aP[i] = A + (size_t)arow * Kk + c4 * 4;
        int gn = n0 + row;
        bV[i] = gn < Nn;
        bP[i] = Wp + (size_t)(bV[i] ? gn : 0) * Kk + c4 * 4;
    }

    int lane = tid & 31, g = lane >> 2, tg = lane & 3;
    int wm = (tid >> 5) & 3;
    int wn = tid >> 7;
    int mbase = wm * 32, nbase = wn * 64;

    float acc[2][8][4];
#pragma unroll
    for (int mt = 0; mt < 2; mt++)
#pragma unroll
        for (int nt = 0; nt < 8; nt++)
#pragma unroll
            for (int q = 0; q < 4; q++) acc[mt][nt][q] = 0.f;

    int nk = Kk / BK;
    float4 ra[2], rb[2];
#pragma unroll
    for (int i = 0; i < 2; i++) {
        ra[i] = aV[i] ? *(const float4*)(aP[i]) : make_float4(0,0,0,0);
        rb[i] = bV[i] ? *(const float4*)(bP[i]) : make_float4(0,0,0,0);
    }

    int buf = 0;
    for (int it = 0; it < nk; it++) {
#pragma unroll
        for (int i = 0; i < 2; i++) {
            int r = rowL[i], w0 = c4L[i] * 2;
            uint32_t h0, l0, h1, l1;
            split2(ra[i].x, ra[i].y, h0, l0);
            split2(ra[i].z, ra[i].w, h1, l1);
            Ah[buf][r][w0] = h0; Ah[buf][r][w0+1] = h1;
            Al[buf][r][w0] = l0; Al[buf][r][w0+1] = l1;
            split2(rb[i].x, rb[i].y, h0, l0);
            split2(rb[i].z, rb[i].w, h1, l1);
            Bh[buf][r][w0] = h0; Bh[buf][r][w0+1] = h1;
            Bl[buf][r][w0] = l0; Bl[buf][r][w0+1] = l1;
        }
        if (it + 1 < nk) {
            int k0 = (it + 1) * BK;
#pragma unroll
            for (int i = 0; i < 2; i++) {
                ra[i] = aV[i] ? *(const float4*)(aP[i] + k0) : make_float4(0,0,0,0);
                rb[i] = bV[i] ? *(const float4*)(bP[i] + k0) : make_float4(0,0,0,0);
            }
        }
        __syncthreads();

        uint32_t ah[2][4], al[2][4];
#pragma unroll
        for (int mt = 0; mt < 2; mt++) {
            int r0 = mbase + mt * 16 + g;
            ah[mt][0] = Ah[buf][r0][tg];     ah[mt][1] = Ah[buf][r0+8][tg];
            ah[mt][2] = Ah[buf][r0][tg+4];   ah[mt][3] = Ah[buf][r0+8][tg+4];
            al[mt][0] = Al[buf][r0][tg];     al[mt][1] = Al[buf][r0+8][tg];
            al[mt][2] = Al[buf][r0][tg+4];   al[mt][3] = Al[buf][r0+8][tg+4];
        }
#pragma unroll
        for (int nt = 0; nt < 8; nt++) {
            int nr = nbase + nt * 8 + g;
            uint32_t bh0 = Bh[buf][nr][tg], bh1 = Bh[buf][nr][tg+4];
            uint32_t bl0 = Bl[buf][nr][tg], bl1 = Bl[buf][nr][tg+4];
#pragma unroll
            for (int mt = 0; mt < 2; mt++) {
                mma_bf16(acc[mt][nt], ah[mt], bh0, bh1);
                mma_bf16(acc[mt][nt], ah[mt], bl0, bl1);
                mma_bf16(acc[mt][nt], al[mt], bh0, bh1);
            }
        }
        buf ^= 1;
    }

#pragma unroll
    for (int mt = 0; mt < 2; mt++) {
#pragma unroll
        for (int nt = 0; nt < 8; nt++) {
            int gc = n0 + nbase + nt * 8 + tg * 2;
            if (gc >= Nn) continue;
            int gm0 = m0 + mbase + mt * 16 + g;
#pragma unroll
            for (int hrow = 0; hrow < 2; hrow++) {
                int gm = gm0 + hrow * 8;
                if (gm >= Mloc) continue;
                int crow = (MODE == 0) ? gm : (base + gm);
                size_t off = (size_t)crow * Nn + gc;
                float2 vv = make_float2(acc[mt][nt][hrow * 2], acc[mt][nt][hrow * 2 + 1]);
                if (MODE == 0 && addp) {
                    float2 rv = *(const float2*)(addp + off);
                    vv.x += rv.x; vv.y += rv.y;
                }
                *(float2*)(C + off) = vv;
            }
        }
    }
}

// ---------------- RMSNorm ----------------
__global__ void rmsnorm_k(const float* __restrict__ x, const float* __restrict__ w,
                          float* __restrict__ o) {
    int n = blockIdx.x;
    const float* xr = x + (size_t)n * D_;
    float s = 0.f;
    for (int d = threadIdx.x; d < D_; d += 256) { float v = xr[d]; s += v * v; }
    __shared__ float red[256];
    red[threadIdx.x] = s; __syncthreads();
    for (int st = 128; st > 0; st >>= 1) {
        if (threadIdx.x < st) red[threadIdx.x] += red[threadIdx.x + st];
        __syncthreads();
    }
    float inv = rsqrtf(red[0] / (float)D_ + 1e-6f);
    float* orow = o + (size_t)n * D_;
    for (int d = threadIdx.x; d < D_; d += 256) orow[d] = xr[d] * inv * w[d];
}

// ---------------- RoPE (in-place on q,k) ----------------
__global__ void rope_k(float* __restrict__ q, float* __restrict__ k,
                       const int* __restrict__ pos) {
    int idx = blockIdx.x * 256 + threadIdx.x;
    if (idx >= NTOK * HN * 64) return;
    int j  = idx & 63;
    int hh = (idx >> 6) & 15;
    int t  = idx >> 10;
    float p = (float)pos[t];
    float inv = expf(-((float)(2 * j) / 128.0f) * 9.210340371976184f);
    float fr = p * inv;
    float sn, cs;
    sincosf(fr, &sn, &cs);
    size_t base = (size_t)t * D_ + hh * HD + j;
    float x1 = q[base], x2 = q[base + 64];
    q[base]      = x1 * cs - x2 * sn;
    q[base + 64] = x2 * cs + x1 * sn;
    x1 = k[base]; x2 = k[base + 64];
    k[base]      = x1 * cs - x2 * sn;
    k[base + 64] = x2 * cs + x1 * sn;
}

// ---------------- split Q/K into bf16 hi/lo ----------------
__global__ void splitqk_k() {
    int i = blockIdx.x * 256 + threadIdx.x;
    if (i >= NTOK * D_) return;
    __nv_bfloat16 h, l;
    split1(g_q[i], h, l); g_qh[i] = h; g_ql[i] = l;
    split1(g_k[i], h, l); g_kh[i] = h; g_kl[i] = l;
}

// ---------------- split V + transpose to [bh][dim][seq] bf16 hi/lo ----------------
__global__ void splitv_k() {
    __shared__ __nv_bfloat16 sh[32][33], sl[32][33];
    int tx = threadIdx.x, ty = threadIdx.y;      // (32, 8)
    int s0 = blockIdx.x * 32;
    int d0 = blockIdx.y * 32;
    int bh = blockIdx.z;
    int b = bh >> 4, hh = bh & 15;
#pragma unroll
    for (int i = 0; i < 4; i++) {
        int sr = ty + i * 8;
        float v = g_v[((size_t)(b * SQ + s0 + sr)) * D_ + hh * HD + d0 + tx];
        __nv_bfloat16 h, l;
        split1(v, h, l);
        sh[sr][tx] = h; sl[sr][tx] = l;
    }
    __syncthreads();
#pragma unroll
    for (int i = 0; i < 4; i++) {
        int dr = ty + i * 8;
        size_t o = ((size_t)bh * HD + d0 + dr) * SQ + s0 + tx;
        g_vth[o] = sh[tx][dr];
        g_vtl[o] = sl[tx][dr];
    }
}

// ---------------- flash attention via mma.sync bf16x3 (no smem, no sync) --------
// grid (SQ/64, HN, BB), block 128. Warp w owns 16 q rows.
__global__ void __launch_bounds__(128) attn_mma_k(float* __restrict__ O)
{
    int w = threadIdx.x >> 5, lane = threadIdx.x & 31;
    int g = lane >> 2, tg = lane & 3;
    int hh = blockIdx.y, b = blockIdx.z;
    int qs0 = blockIdx.x * 64 + w * 16;
    int bh = b * HN + hh;

    // Q fragments (hi/lo), rows g and g+8
    uint32_t qfh[8][4], qfl[8][4];
    size_t qr0 = ((size_t)(b * SQ + qs0 + g)) * D_ + hh * HD;
    size_t qr1 = qr0 + (size_t)8 * D_;
#pragma unroll
    for (int ks = 0; ks < 8; ks++) {
        int c0 = ks * 16 + 2 * tg;
        qfh[ks][0] = *(const uint32_t*)&g_qh[qr0 + c0];
        qfh[ks][1] = *(const uint32_t*)&g_qh[qr1 + c0];
        qfh[ks][2] = *(const uint32_t*)&g_qh[qr0 + c0 + 8];
        qfh[ks][3] = *(const uint32_t*)&g_qh[qr1 + c0 + 8];
        qfl[ks][0] = *(const uint32_t*)&g_ql[qr0 + c0];
        qfl[ks][1] = *(const uint32_t*)&g_ql[qr1 + c0];
        qfl[ks][2] = *(const uint32_t*)&g_ql[qr0 + c0 + 8];
        qfl[ks][3] = *(const uint32_t*)&g_ql[qr1 + c0 + 8];
    }

    float m0 = -1e30f, m1 = -1e30f, l0 = 0.f, l1 = 0.f;
    float Oa[16][4];
#pragma unroll
    for (int nt = 0; nt < 16; nt++)
#pragma unroll
        for (int q = 0; q < 4; q++) Oa[nt][q] = 0.f;

    const float SC = 0.08838834764831845f;   // 1/sqrt(128)
    int row0 = qs0 + g, row1 = row0 + 8;

    for (int kt = 0; kt <= qs0 + 15; kt += 32) {
        // ---- S = Q K^T (16x32) ----
        float s[4][4];
#pragma unroll
        for (int nt = 0; nt < 4; nt++)
#pragma unroll
            for (int q = 0; q < 4; q++) s[nt][q] = 0.f;

        size_t kb = ((size_t)(b * SQ + kt)) * D_ + hh * HD;
#pragma unroll
        for (int ks = 0; ks < 8; ks++) {
            int c0 = ks * 16 + 2 * tg;
#pragma unroll
            for (int nt = 0; nt < 4; nt++) {
                size_t kr = kb + (size_t)(nt * 8 + g) * D_;
                uint32_t bh0 = *(const uint32_t*)&g_kh[kr + c0];
                uint32_t bh1 = *(const uint32_t*)&g_kh[kr + c0 + 8];
                uint32_t bl0 = *(const uint32_t*)&g_kl[kr + c0];
                uint32_t bl1 = *(const uint32_t*)&g_kl[kr + c0 + 8];
                mma_bf16(s[nt], qfh[ks], bh0, bh1);
                mma_bf16(s[nt], qfh[ks], bl0, bl1);
                mma_bf16(s[nt], qfl[ks], bh0, bh1);
            }
        }

        // ---- scale + causal mask ----
#pragma unroll
        for (int nt = 0; nt < 4; nt++) {
            int col = kt + nt * 8 + 2 * tg;
            s[nt][0] = (col     <= row0) ? s[nt][0] * SC : -1e30f;
            s[nt][1] = (col + 1 <= row0) ? s[nt][1] * SC : -1e30f;
            s[nt][2] = (col     <= row1) ? s[nt][2] * SC : -1e30f;
            s[nt][3] = (col + 1 <= row1) ? s[nt][3] * SC : -1e30f;
        }

        // ---- online softmax (row stats over quad) ----
        float mx0 = -1e30f, mx1 = -1e30f;
#pragma unroll
        for (int nt = 0; nt < 4; nt++) {
            mx0 = fmaxf(mx0, fmaxf(s[nt][0], s[nt][1]));
            mx1 = fmaxf(mx1, fmaxf(s[nt][2], s[nt][3]));
        }
        mx0 = fmaxf(mx0, __shfl_xor_sync(0xffffffff, mx0, 1));
        mx0 = fmaxf(mx0, __shfl_xor_sync(0xffffffff, mx0, 2));
        mx1 = fmaxf(mx1, __shfl_xor_sync(0xffffffff, mx1, 1));
        mx1 = fmaxf(mx1, __shfl_xor_sync(0xffffffff, mx1, 2));
        float mn0 = fmaxf(m0, mx0), mn1 = fmaxf(m1, mx1);
        float a0 = __expf(m0 - mn0), a1 = __expf(m1 - mn1);
        float sum0 = 0.f, sum1 = 0.f;
#pragma unroll
        for (int nt = 0; nt < 4; nt++) {
            s[nt][0] = __expf(s[nt][0] - mn0);
            s[nt][1] = __expf(s[nt][1] - mn0);
            s[nt][2] = __expf(s[nt][2] - mn1);
            s[nt][3] = __expf(s[nt][3] - mn1);
            sum0 += s[nt][0] + s[nt][1];
            sum1 += s[nt][2] + s[nt][3];
        }
        sum0 += __shfl_xor_sync(0xffffffff, sum0, 1);
        sum0 += __shfl_xor_sync(0xffffffff, sum0, 2);
        sum1 += __shfl_xor_sync(0xffffffff, sum1, 1);
        sum1 += __shfl_xor_sync(0xffffffff, sum1, 2);
        l0 = l0 * a0 + sum0; l1 = l1 * a1 + sum1;
        m0 = mn0; m1 = mn1;

        // ---- rescale accumulator ----
#pragma unroll
        for (int nt = 0; nt < 16; nt++) {
            Oa[nt][0] *= a0; Oa[nt][1] *= a0;
            Oa[nt][2] *= a1; Oa[nt][3] *= a1;
        }

        // ---- pack P fragments (hi/lo) ----
        uint32_t pah[2][4], pal[2][4];
#pragma unroll
        for (int ks2 = 0; ks2 < 2; ks2++) {
            int na = ks2 * 2, nb = na + 1;
            split2(s[na][0], s[na][1], pah[ks2][0], pal[ks2][0]);
            split2(s[na][2], s[na][3], pah[ks2][1], pal[ks2][1]);
            split2(s[nb][0], s[nb][1], pah[ks2][2], pal[ks2][2]);
            split2(s[nb][2], s[nb][3], pah[ks2][3], pal[ks2][3]);
        }

        // ---- O += P V ----
#pragma unroll
        for (int ks2 = 0; ks2 < 2; ks2++) {
            int st = kt + ks2 * 16 + 2 * tg;
#pragma unroll
            for (int nt = 0; nt < 16; nt++) {
                size_t vr = ((size_t)bh * HD + nt * 8 + g) * SQ + st;
                uint32_t vh0 = *(const uint32_t*)&g_vth[vr];
                uint32_t vh1 = *(const uint32_t*)&g_vth[vr + 8];
                uint32_t vl0 = *(const uint32_t*)&g_vtl[vr];
                uint32_t vl1 = *(const uint32_t*)&g_vtl[vr + 8];
                mma_bf16(Oa[nt], pah[ks2], vh0, vh1);
                mma_bf16(Oa[nt], pah[ks2], vl0, vl1);
                mma_bf16(Oa[nt], pal[ks2], vh0, vh1);
            }
        }
    }

    // ---- epilogue ----
    float i0 = 1.f / l0, i1 = 1.f / l1;
    size_t or0 = ((size_t)(b * SQ + qs0 + g)) * D_ + hh * HD;
    size_t or1 = or0 + (size_t)8 * D_;
#pragma unroll
    for (int nt = 0; nt < 16; nt++) {
        int col = nt * 8 + 2 * tg;
        *(float2*)&O[or0 + col] = make_float2(Oa[nt][0] * i0, Oa[nt][1] * i0);
        *(float2*)&O[or1 + col] = make_float2(Oa[nt][2] * i1, Oa[nt][3] * i1);
    }
}

// ---------------- MoE routing ----------------
__global__ void zero_k() {
    if (threadIdx.x < EE) { g_cnt[threadIdx.x] = 0; g_cur[threadIdx.x] = 0; }
}

__global__ void route1_k(const float* __restrict__ x, const float* __restrict__ gw) {
    int n = blockIdx.x;
    float part[EE];
#pragma unroll
    for (int e = 0; e < EE; e++) part[e] = 0.f;
    for (int d = threadIdx.x; d < D_; d += 256) {
        float xv = x[(size_t)n * D_ + d];
#pragma unroll
        for (int e = 0; e < EE; e++) part[e] = fmaf(xv, gw[e * D_ + d], part[e]);
    }
    __shared__ float red[256];
    __shared__ float lg[EE];
    for (int e = 0; e < EE; e++) {
        red[threadIdx.x] = part[e]; __syncthreads();
        for (int st = 128; st > 0; st >>= 1) {
            if (threadIdx.x < st) red[threadIdx.x] += red[threadIdx.x + st];
            __syncthreads();
        }
        if (threadIdx.x == 0) lg[e] = red[0];
        __syncthreads();
    }
    if (threadIdx.x == 0) {
        int i0 = 0; float b0 = lg[0];
        for (int e = 1; e < EE; e++) if (lg[e] > b0) { b0 = lg[e]; i0 = e; }
        int i1 = -1; float b1 = -1e30f;
        for (int e = 0; e < EE; e++) { if (e == i0) continue; if (lg[e] > b1) { b1 = lg[e]; i1 = e; } }
        float m = fmaxf(b0, b1);
        float w0 = __expf(b0 - m), w1 = __expf(b1 - m);
        float s = w0 + w1; w0 /= s; w1 /= s;
        g_tope[n*2] = i0; g_tope[n*2+1] = i1;
        g_topw[n*2] = w0; g_topw[n*2+1] = w1;
        atomicAdd(&g_cnt[i0], 1); atomicAdd(&g_cnt[i1], 1);
    }
}

__global__ void scan_k() {
    int o = 0;
    for (int e = 0; e < EE; e++) { g_off[e] = o; o += g_cnt[e]; }
}

__global__ void assign_k() {
    int n = blockIdx.x * 256 + threadIdx.x;
    if (n >= NTOK) return;
#pragma unroll
    for (int kk = 0; kk < 2; kk++) {
        int e = g_tope[n*2 + kk];
        int p = g_off[e] + atomicAdd(&g_cur[e], 1);
        g_slot_tok[p] = n;
        g_slot_w[p]   = g_topw[n*2 + kk];
        g_tok_pos[n*2 + kk] = p;
    }
}

__global__ void swiglu_k() {
    int i = blockIdx.x * 256 + threadIdx.x;
    if (i >= NSLOT * DE_) return;
    float g = g_gb[i], u = g_ub[i];
    float sig = 1.f / (1.f + __expf(-g));
    g_gb[i] = g * sig * u;
}

__global__ void final_k(float* __restrict__ out) {
    int n = blockIdx.x;
    int p0 = g_tok_pos[n*2], p1 = g_tok_pos[n*2 + 1];
    float w0 = g_slot_w[p0], w1 = g_slot_w[p1];
    size_t hb = (size_t)n * D_;
    for (int d = threadIdx.x * 4; d < D_; d += 1024) {
        float4 hv = *(const float4*)(g_h + hb + d);
        float4 a  = *(const float4*)(g_op + (size_t)p0 * D_ + d);
        float4 b4 = *(const float4*)(g_op + (size_t)p1 * D_ + d);
        float4 o;
        o.x = hv.x + w0 * a.x + w1 * b4.x;
        o.y = hv.y + w0 * a.y + w1 * b4.y;
        o.z = hv.z + w0 * a.z + w1 * b4.z;
        o.w = hv.w + w0 * a.w + w1 * b4.w;
        *(float4*)(out + hb + d) = o;
    }
}

// ---------------- launcher ----------------
extern "C" void kernel_launch(void* const* d_in, const int* in_sizes, int n_in,
                              void* d_out, int out_size) {
    const float* hidden = (const float*)d_in[0];
    const float* ln1    = (const float*)d_in[1];
    const float* ln2    = (const float*)d_in[2];
    const float* qw     = (const float*)d_in[3];
    const float* kw     = (const float*)d_in[4];
    const float* vw     = (const float*)d_in[5];
    const float* ow     = (const float*)d_in[6];
    const float* gw     = (const float*)d_in[7];
    const float* egw    = (const float*)d_in[8];
    const float* euw    = (const float*)d_in[9];
    const float* edw    = (const float*)d_in[10];
    const int*   pos    = (const int*)d_in[11];
    float* out = (float*)d_out;

    float *xn, *qb, *kb, *vb, *ab, *hb, *x2, *gb, *ub, *op;
    cudaGetSymbolAddress((void**)&xn, g_xn);
    cudaGetSymbolAddress((void**)&qb, g_q);
    cudaGetSymbolAddress((void**)&kb, g_k);
    cudaGetSymbolAddress((void**)&vb, g_v);
    cudaGetSymbolAddress((void**)&ab, g_attn);
    cudaGetSymbolAddress((void**)&hb, g_h);
    cudaGetSymbolAddress((void**)&x2, g_xn2);
    cudaGetSymbolAddress((void**)&gb, g_gb);
    cudaGetSymbolAddress((void**)&ub, g_ub);
    cudaGetSymbolAddress((void**)&op, g_op);

    // 1. pre-attention RMSNorm
    rmsnorm_k<<<NTOK, 256>>>(hidden, ln1, xn);

    // 2. QKV projections (mma.sync bf16x3)
    dim3 gdense(D_ / TN, NTOK / TM, 1);
    gemm_mma<0><<<gdense, 256>>>(xn, qw, qb, nullptr, NTOK, D_, D_, 0);
    gemm_mma<0><<<gdense, 256>>>(xn, kw, kb, nullptr, NTOK, D_, D_, 0);
    gemm_mma<0><<<gdense, 256>>>(xn, vw, vb, nullptr, NTOK, D_, D_, 0);

    // 3. RoPE
    rope_k<<<(NTOK * HN * 64) / 256, 256>>>(qb, kb, pos);

    // 4. split to bf16 hi/lo (+ V transpose), then mma flash attention
    splitqk_k<<<(NTOK * D_) / 256, 256>>>();
    splitv_k<<<dim3(SQ / 32, HD / 32, BB * HN), dim3(32, 8)>>>();
    attn_mma_k<<<dim3(SQ / 64, HN, BB), 128>>>(ab);

    // 5. O projection + residual
    gemm_mma<0><<<gdense, 256>>>(ab, ow, hb, hidden, NTOK, D_, D_, 0);

    // 6. post-attention RMSNorm
    rmsnorm_k<<<NTOK, 256>>>(hb, ln2, x2);

    // 7. routing
    zero_k<<<1, 32>>>();
    route1_k<<<NTOK, 256>>>(x2, gw);
    scan_k<<<1, 1>>>();
    assign_k<<<NTOK / 256, 256>>>();

    // 8. MoE expert GEMMs (mma.sync bf16x3, gathered rows)
    gemm_mma<1><<<dim3((DE_ + TN - 1) / TN, 16, EE), 256>>>(
        x2, egw, gb, nullptr, 0, DE_, D_, (long)DE_ * D_);
    gemm_mma<1><<<dim3((DE_ + TN - 1) / TN, 16, EE), 256>>>(
        x2, euw, ub, nullptr, 0, DE_, D_, (long)DE_ * D_);
    swiglu_k<<<(NSLOT * DE_ + 255) / 256, 256>>>();
    gemm_mma<2><<<dim3(D_ / TN, 16, EE), 256>>>(
        gb, edw, op, nullptr, 0, D_, DE_, (long)D_ * DE_);

    // 9. weighted combine + residual
    final_k<<<NTOK, 256>>>(out);
}